// round 5
// baseline (speedup 1.0000x reference)
#include <cuda_runtime.h>
#include <cuda_fp16.h>
#include <cstdint>

// ---------------------------------------------------------------------------
// Problem constants
// ---------------------------------------------------------------------------
#define K_DIM 4096
#define N_DIM 4096
#define M_MAX 8192

// GEMM tiling: 128x128 CTA tile, 3-stage cp.async pipeline, 2 CTAs/SM
#define BM 128
#define BN 128
#define BKH 64                       // K halfs per stage = 128 bytes per row
#define STAGES 3
#define NT (K_DIM / BKH)             // 64 K-tiles

#define A_TILE_BYTES (BM * BKH * 2)  // 16 KB
#define B_TILE_BYTES (BN * BKH * 2)  // 16 KB
#define STAGE_BYTES  (A_TILE_BYTES + B_TILE_BYTES)   // 32 KB
#define SMEM_TOTAL   (STAGES * STAGE_BYTES)          // 96 KB

// Scratch: W transposed [N][K] fp16, x [M][K] fp16
__device__ __half g_w16[(size_t)N_DIM * K_DIM];
__device__ __half g_x16[(size_t)M_MAX * K_DIM];

// ---------------------------------------------------------------------------
// Helpers
// ---------------------------------------------------------------------------
__device__ __forceinline__ uint32_t smem_u32(const void* p) {
    uint32_t a;
    asm("{ .reg .u64 t; cvta.to.shared.u64 t, %1; cvt.u32.u64 %0, t; }"
        : "=r"(a) : "l"(p));
    return a;
}
__device__ __forceinline__ void cp_async16(uint32_t s, const void* g) {
    asm volatile("cp.async.cg.shared.global [%0], [%1], 16;" :: "r"(s), "l"(g));
}
__device__ __forceinline__ void cp_commit() {
    asm volatile("cp.async.commit_group;" ::: "memory");
}
template <int N>
__device__ __forceinline__ void cp_wait() {
    asm volatile("cp.async.wait_group %0;" :: "n"(N) : "memory");
}
__device__ __forceinline__ void ldsm4(uint32_t& r0, uint32_t& r1, uint32_t& r2,
                                      uint32_t& r3, uint32_t addr) {
    asm volatile("ldmatrix.sync.aligned.m8n8.x4.shared.b16 {%0,%1,%2,%3}, [%4];"
                 : "=r"(r0), "=r"(r1), "=r"(r2), "=r"(r3) : "r"(addr));
}
__device__ __forceinline__ void mma_f16(float& c0, float& c1, float& c2, float& c3,
                                        uint32_t a0, uint32_t a1, uint32_t a2,
                                        uint32_t a3, uint32_t b0, uint32_t b1) {
    asm volatile(
        "mma.sync.aligned.m16n8k16.row.col.f32.f16.f16.f32 "
        "{%0,%1,%2,%3}, {%4,%5,%6,%7}, {%8,%9}, {%0,%1,%2,%3};"
        : "+f"(c0), "+f"(c1), "+f"(c2), "+f"(c3)
        : "r"(a0), "r"(a1), "r"(a2), "r"(a3), "r"(b0), "r"(b1));
}

// ---------------------------------------------------------------------------
// Pass 1 (fused): x -> fp16 scratch  AND  dequant W -> transposed fp16 scratch
//   blocks [0, xblocks):        x conversion, 8 floats / thread
//   blocks [xblocks, +wblocks): int4 dequant, 8 weights / thread
// ---------------------------------------------------------------------------
__global__ __launch_bounds__(256) void prep_kernel(const float* __restrict__ x,
                                                   const int* __restrict__ qweight,
                                                   const float* __restrict__ scales,
                                                   const int* __restrict__ qzeros,
                                                   int xblocks) {
    if ((int)blockIdx.x < xblocks) {
        int idx = blockIdx.x * blockDim.x + threadIdx.x;   // [0, M*K/8)
        const float4* x4 = (const float4*)x;
        float4 v0 = x4[2 * idx];
        float4 v1 = x4[2 * idx + 1];
        __half2 h[4];
        h[0] = __floats2half2_rn(v0.x, v0.y);
        h[1] = __floats2half2_rn(v0.z, v0.w);
        h[2] = __floats2half2_rn(v1.x, v1.y);
        h[3] = __floats2half2_rn(v1.z, v1.w);
        *(uint4*)&g_x16[(size_t)idx * 8] = *(uint4*)h;
    } else {
        int idx = (blockIdx.x - xblocks) * blockDim.x + threadIdx.x;  // [0, N*K/8)
        int p = idx & (K_DIM / 8 - 1);   // packed-k index 0..511
        int n = idx >> 9;
        int packed = qweight[p * N_DIM + n];
        int g = p >> 4;                  // group = (p*8)/128
        float s = scales[g * N_DIM + n];
        int zp = qzeros[g * (N_DIM / 8) + (n >> 3)];
        float z = (float)(((zp >> ((n & 7) * 4)) & 15) + 1);
        __half2 h[4];
#pragma unroll
        for (int i = 0; i < 4; i++) {
            float w0 = ((float)((packed >> (8 * i)) & 15) - z) * s;
            float w1 = ((float)((packed >> (8 * i + 4)) & 15) - z) * s;
            h[i] = __floats2half2_rn(w0, w1);
        }
        *(uint4*)&g_w16[(size_t)n * K_DIM + p * 8] = *(uint4*)h;
    }
}

// ---------------------------------------------------------------------------
// Pass 2: fp16 mma.sync GEMM.  out[M,N] = x16[M,K] @ w16[N,K]^T + bias
// CTA 128x128, BKH=64, 3-stage cp.async, 8 warps of 32x64, 2 CTAs/SM.
// Fill for tile t+2 is issued BEFORE computing tile t (loads overlap MMAs).
// ---------------------------------------------------------------------------
__device__ __forceinline__ void fill_stage(uint32_t stage_base, const __half* gA,
                                           const __half* gB, int tid) {
    uint32_t sA = stage_base;
    uint32_t sB = stage_base + A_TILE_BYTES;
#pragma unroll
    for (int i = 0; i < 4; i++) {                 // A: 128 rows x 8 chunks
        int c = tid + i * 256;
        int r = c >> 3, cc = c & 7;
        cp_async16(sA + r * 128 + ((cc ^ (r & 7)) << 4), gA + (size_t)r * K_DIM + cc * 8);
    }
#pragma unroll
    for (int i = 0; i < 4; i++) {                 // B: 128 rows x 8 chunks
        int c = tid + i * 256;
        int r = c >> 3, cc = c & 7;
        cp_async16(sB + r * 128 + ((cc ^ (r & 7)) << 4), gB + (size_t)r * K_DIM + cc * 8);
    }
}

__global__ __launch_bounds__(256, 2) void gemm_f16_kernel(const float* __restrict__ bias,
                                                          float* __restrict__ out) {
    extern __shared__ char smem[];
    const uint32_t sbase = smem_u32(smem);
    const int tid = threadIdx.x;
    const int wid = tid >> 5;
    const int lane = tid & 31;
    const int warp_m = (wid & 3) * 32;            // 4 warps along M (32 rows each)
    const int warp_n = (wid >> 2) * 64;           // 2 warps along N (64 cols each)
    const int bm = blockIdx.y * BM;
    const int bn = blockIdx.x * BN;

    float c[2][8][4];
#pragma unroll
    for (int i = 0; i < 2; i++)
#pragma unroll
        for (int j = 0; j < 8; j++)
#pragma unroll
            for (int q = 0; q < 4; q++) c[i][j][q] = 0.0f;

    const __half* gA0 = &g_x16[(size_t)bm * K_DIM];
    const __half* gB0 = &g_w16[(size_t)bn * K_DIM];

    // ldmatrix per-thread row/chunk bases
    const int a_row = warp_m + (lane & 15);
    const int a_r7 = a_row & 7;
    const int a_chi = lane >> 4;                  // chunk offset 0/1
    const int b_row = warp_n + ((lane >> 4) << 3) + (lane & 7);
    const int b_r7 = b_row & 7;
    const int b_clo = (lane >> 3) & 1;

    // Prologue: fill stages 0..STAGES-2
#pragma unroll
    for (int t = 0; t < STAGES - 1; t++) {
        fill_stage(sbase + t * STAGE_BYTES, gA0 + t * BKH, gB0 + t * BKH, tid);
        cp_commit();
    }

    int slot = 0;        // slot of tile t
    int fslot = STAGES - 1;  // slot of tile t + STAGES - 1
    for (int t = 0; t < NT; t++) {
        cp_wait<STAGES - 2>();
        __syncthreads();

        // Issue next fill FIRST so global loads overlap this tile's MMAs.
        const int f = t + STAGES - 1;
        if (f < NT) {
            fill_stage(sbase + fslot * STAGE_BYTES,
                       gA0 + (size_t)f * BKH, gB0 + (size_t)f * BKH, tid);
        }
        cp_commit();

        const uint32_t sA = sbase + slot * STAGE_BYTES;
        const uint32_t sB = sA + A_TILE_BYTES;
#pragma unroll
        for (int s = 0; s < 4; s++) {             // 4 k16-steps per tile
            uint32_t a[2][4];
#pragma unroll
            for (int i = 0; i < 2; i++) {
                int r = a_row + 16 * i;
                uint32_t addr = sA + r * 128 + (((2 * s + a_chi) ^ a_r7) << 4);
                ldsm4(a[i][0], a[i][1], a[i][2], a[i][3], addr);
            }
            uint32_t b[8][2];
#pragma unroll
            for (int jp = 0; jp < 4; jp++) {
                int r = b_row + 16 * jp;
                uint32_t addr = sB + r * 128 + (((2 * s + b_clo) ^ b_r7) << 4);
                ldsm4(b[2 * jp][0], b[2 * jp][1], b[2 * jp + 1][0], b[2 * jp + 1][1], addr);
            }
#pragma unroll
            for (int i = 0; i < 2; i++)
#pragma unroll
                for (int j = 0; j < 8; j++)
                    mma_f16(c[i][j][0], c[i][j][1], c[i][j][2], c[i][j][3],
                            a[i][0], a[i][1], a[i][2], a[i][3], b[j][0], b[j][1]);
        }

        if (++slot == STAGES) slot = 0;
        if (++fslot == STAGES) fslot = 0;
    }

    // Epilogue: add bias, store fp32
#pragma unroll
    for (int i = 0; i < 2; i++) {
#pragma unroll
        for (int j = 0; j < 8; j++) {
            const int row = bm + warp_m + i * 16 + (lane >> 2);
            const int col = bn + warp_n + j * 8 + (lane & 3) * 2;
            const float b0 = bias[col];
            const float b1 = bias[col + 1];
            *(float2*)&out[(size_t)row * N_DIM + col] =
                make_float2(c[i][j][0] + b0, c[i][j][1] + b1);
            *(float2*)&out[(size_t)(row + 8) * N_DIM + col] =
                make_float2(c[i][j][2] + b0, c[i][j][3] + b1);
        }
    }
}

// ---------------------------------------------------------------------------
// Launch
// ---------------------------------------------------------------------------
extern "C" void kernel_launch(void* const* d_in, const int* in_sizes, int n_in,
                              void* d_out, int out_size) {
    const float* x       = (const float*)d_in[0];
    const int*   qweight = (const int*)d_in[1];
    const float* scales  = (const float*)d_in[2];
    const int*   qzeros  = (const int*)d_in[3];
    const float* bias    = (const float*)d_in[4];
    float* out = (float*)d_out;

    const int M = in_sizes[0] / K_DIM;  // 8192

    // Pass 1: fused x->fp16 + W dequant
    {
        int xblocks = (M * K_DIM / 8) / 256;        // 16384
        int wblocks = ((K_DIM / 8) * N_DIM) / 256;  // 8192
        prep_kernel<<<xblocks + wblocks, 256>>>(x, qweight, scales, qzeros, xblocks);
    }
    // Pass 2: GEMM
    {
        cudaFuncSetAttribute(gemm_f16_kernel,
                             cudaFuncAttributeMaxDynamicSharedMemorySize, SMEM_TOTAL);
        dim3 grid(N_DIM / BN, M / BM);
        gemm_f16_kernel<<<grid, 256, SMEM_TOTAL>>>(bias, out);
    }
}

// round 6
// speedup vs baseline: 1.0419x; 1.0419x over previous
#include <cuda_runtime.h>
#include <cuda_fp16.h>
#include <cstdint>

// ---------------------------------------------------------------------------
// Problem constants
// ---------------------------------------------------------------------------
#define K_DIM 4096
#define N_DIM 4096
#define M_MAX 8192

// GEMM tiling: 128x128 CTA tile, 3-stage cp.async pipeline, 2 CTAs/SM
#define BM 128
#define BN 128
#define BKH 64                       // K halfs per stage = 128 bytes per row
#define STAGES 3
#define NT (K_DIM / BKH)             // 64 K-tiles

#define A_TILE_BYTES (BM * BKH * 2)  // 16 KB
#define B_TILE_BYTES (BN * BKH * 2)  // 16 KB
#define STAGE_BYTES  (A_TILE_BYTES + B_TILE_BYTES)   // 32 KB
#define SMEM_TOTAL   (STAGES * STAGE_BYTES)          // 96 KB

// Scratch: W transposed [N][K] fp16, x [M][K] fp16
__device__ __half g_w16[(size_t)N_DIM * K_DIM];
__device__ __half g_x16[(size_t)M_MAX * K_DIM];

// ---------------------------------------------------------------------------
// Helpers
// ---------------------------------------------------------------------------
__device__ __forceinline__ uint32_t smem_u32(const void* p) {
    uint32_t a;
    asm("{ .reg .u64 t; cvta.to.shared.u64 t, %1; cvt.u32.u64 %0, t; }"
        : "=r"(a) : "l"(p));
    return a;
}
__device__ __forceinline__ void cp_async16(uint32_t s, const void* g) {
    asm volatile("cp.async.cg.shared.global [%0], [%1], 16;" :: "r"(s), "l"(g));
}
__device__ __forceinline__ void cp_commit() {
    asm volatile("cp.async.commit_group;" ::: "memory");
}
template <int N>
__device__ __forceinline__ void cp_wait() {
    asm volatile("cp.async.wait_group %0;" :: "n"(N) : "memory");
}
__device__ __forceinline__ void ldsm4(uint32_t& r0, uint32_t& r1, uint32_t& r2,
                                      uint32_t& r3, uint32_t addr) {
    asm volatile("ldmatrix.sync.aligned.m8n8.x4.shared.b16 {%0,%1,%2,%3}, [%4];"
                 : "=r"(r0), "=r"(r1), "=r"(r2), "=r"(r3) : "r"(addr));
}
__device__ __forceinline__ void mma_f16(float& c0, float& c1, float& c2, float& c3,
                                        uint32_t a0, uint32_t a1, uint32_t a2,
                                        uint32_t a3, uint32_t b0, uint32_t b1) {
    asm volatile(
        "mma.sync.aligned.m16n8k16.row.col.f32.f16.f16.f32 "
        "{%0,%1,%2,%3}, {%4,%5,%6,%7}, {%8,%9}, {%0,%1,%2,%3};"
        : "+f"(c0), "+f"(c1), "+f"(c2), "+f"(c3)
        : "r"(a0), "r"(a1), "r"(a2), "r"(a3), "r"(b0), "r"(b1));
}

// ---------------------------------------------------------------------------
// Pass 1 (fused): x -> fp16 scratch  AND  dequant W -> transposed fp16 scratch
// ---------------------------------------------------------------------------
__global__ __launch_bounds__(256) void prep_kernel(const float* __restrict__ x,
                                                   const int* __restrict__ qweight,
                                                   const float* __restrict__ scales,
                                                   const int* __restrict__ qzeros,
                                                   int xblocks) {
    if ((int)blockIdx.x < xblocks) {
        int idx = blockIdx.x * blockDim.x + threadIdx.x;   // [0, M*K/8)
        const float4* x4 = (const float4*)x;
        float4 v0 = x4[2 * idx];
        float4 v1 = x4[2 * idx + 1];
        __half2 h[4];
        h[0] = __floats2half2_rn(v0.x, v0.y);
        h[1] = __floats2half2_rn(v0.z, v0.w);
        h[2] = __floats2half2_rn(v1.x, v1.y);
        h[3] = __floats2half2_rn(v1.z, v1.w);
        *(uint4*)&g_x16[(size_t)idx * 8] = *(uint4*)h;
    } else {
        int idx = (blockIdx.x - xblocks) * blockDim.x + threadIdx.x;  // [0, N*K/8)
        int p = idx & (K_DIM / 8 - 1);   // packed-k index 0..511
        int n = idx >> 9;
        int packed = qweight[p * N_DIM + n];
        int g = p >> 4;                  // group = (p*8)/128
        float s = scales[g * N_DIM + n];
        int zp = qzeros[g * (N_DIM / 8) + (n >> 3)];
        float z = (float)(((zp >> ((n & 7) * 4)) & 15) + 1);
        __half2 h[4];
#pragma unroll
        for (int i = 0; i < 4; i++) {
            float w0 = ((float)((packed >> (8 * i)) & 15) - z) * s;
            float w1 = ((float)((packed >> (8 * i + 4)) & 15) - z) * s;
            h[i] = __floats2half2_rn(w0, w1);
        }
        *(uint4*)&g_w16[(size_t)n * K_DIM + p * 8] = *(uint4*)h;
    }
}

// ---------------------------------------------------------------------------
// Pass 2: fp16 mma.sync GEMM.  out[M,N] = x16[M,K] @ w16[N,K]^T + bias
// CTA 128x128, BKH=64, 3-stage cp.async, 8 warps of 32x64, 2 CTAs/SM.
// Fill for tile t+2 is issued piecewise, one quarter after each k16 step,
// so LSU issue pressure is uniform and never blocks the tile-head LDSMs.
// ---------------------------------------------------------------------------
__device__ __forceinline__ void fill_piece(uint32_t stage_base, const __half* gA,
                                           const __half* gB, int tid, int piece) {
    uint32_t sA = stage_base;
    uint32_t sB = stage_base + A_TILE_BYTES;
    int c = tid + piece * 256;
    int r = c >> 3, cc = c & 7;
    cp_async16(sA + r * 128 + ((cc ^ (r & 7)) << 4), gA + (size_t)r * K_DIM + cc * 8);
    cp_async16(sB + r * 128 + ((cc ^ (r & 7)) << 4), gB + (size_t)r * K_DIM + cc * 8);
}

__global__ __launch_bounds__(256, 2) void gemm_f16_kernel(const float* __restrict__ bias,
                                                          float* __restrict__ out) {
    extern __shared__ char smem[];
    const uint32_t sbase = smem_u32(smem);
    const int tid = threadIdx.x;
    const int wid = tid >> 5;
    const int lane = tid & 31;
    const int warp_m = (wid & 3) * 32;            // 4 warps along M (32 rows each)
    const int warp_n = (wid >> 2) * 64;           // 2 warps along N (64 cols each)
    const int bm = blockIdx.y * BM;
    const int bn = blockIdx.x * BN;

    float c[2][8][4];
#pragma unroll
    for (int i = 0; i < 2; i++)
#pragma unroll
        for (int j = 0; j < 8; j++)
#pragma unroll
            for (int q = 0; q < 4; q++) c[i][j][q] = 0.0f;

    const __half* gA0 = &g_x16[(size_t)bm * K_DIM];
    const __half* gB0 = &g_w16[(size_t)bn * K_DIM];

    // ldmatrix per-thread row/chunk bases
    const int a_row = warp_m + (lane & 15);
    const int a_r7 = a_row & 7;
    const int a_chi = lane >> 4;                  // chunk offset 0/1
    const int b_row = warp_n + ((lane >> 4) << 3) + (lane & 7);
    const int b_r7 = b_row & 7;
    const int b_clo = (lane >> 3) & 1;

    // Prologue: fill stages 0..STAGES-2 completely
#pragma unroll
    for (int t = 0; t < STAGES - 1; t++) {
#pragma unroll
        for (int piece = 0; piece < 4; piece++)
            fill_piece(sbase + t * STAGE_BYTES, gA0 + t * BKH, gB0 + t * BKH, tid, piece);
        cp_commit();
    }

    int slot = 0;            // slot of tile t
    int fslot = STAGES - 1;  // slot of tile t + STAGES - 1
    for (int t = 0; t < NT; t++) {
        cp_wait<STAGES - 2>();
        __syncthreads();

        const int f = t + STAGES - 1;
        const bool do_fill = (f < NT);
        const uint32_t fbase = sbase + fslot * STAGE_BYTES;
        const __half* fA = gA0 + (size_t)f * BKH;
        const __half* fB = gB0 + (size_t)f * BKH;

        const uint32_t sA = sbase + slot * STAGE_BYTES;
        const uint32_t sB = sA + A_TILE_BYTES;
#pragma unroll
        for (int s = 0; s < 4; s++) {             // 4 k16-steps per tile
            uint32_t a[2][4];
#pragma unroll
            for (int i = 0; i < 2; i++) {
                int r = a_row + 16 * i;
                uint32_t addr = sA + r * 128 + (((2 * s + a_chi) ^ a_r7) << 4);
                ldsm4(a[i][0], a[i][1], a[i][2], a[i][3], addr);
            }
            uint32_t b[8][2];
#pragma unroll
            for (int jp = 0; jp < 4; jp++) {
                int r = b_row + 16 * jp;
                uint32_t addr = sB + r * 128 + (((2 * s + b_clo) ^ b_r7) << 4);
                ldsm4(b[2 * jp][0], b[2 * jp][1], b[2 * jp + 1][0], b[2 * jp + 1][1], addr);
            }
#pragma unroll
            for (int i = 0; i < 2; i++)
#pragma unroll
                for (int j = 0; j < 8; j++)
                    mma_f16(c[i][j][0], c[i][j][1], c[i][j][2], c[i][j][3],
                            a[i][0], a[i][1], a[i][2], a[i][3], b[j][0], b[j][1]);

            // One quarter of the t+2 fill after each compute step.
            if (do_fill) fill_piece(fbase, fA, fB, tid, s);
        }
        cp_commit();

        if (++slot == STAGES) slot = 0;
        if (++fslot == STAGES) fslot = 0;
    }

    // Epilogue: add bias, store fp32
#pragma unroll
    for (int i = 0; i < 2; i++) {
#pragma unroll
        for (int j = 0; j < 8; j++) {
            const int row = bm + warp_m + i * 16 + (lane >> 2);
            const int col = bn + warp_n + j * 8 + (lane & 3) * 2;
            const float b0 = bias[col];
            const float b1 = bias[col + 1];
            *(float2*)&out[(size_t)row * N_DIM + col] =
                make_float2(c[i][j][0] + b0, c[i][j][1] + b1);
            *(float2*)&out[(size_t)(row + 8) * N_DIM + col] =
                make_float2(c[i][j][2] + b0, c[i][j][3] + b1);
        }
    }
}

// ---------------------------------------------------------------------------
// Launch
// ---------------------------------------------------------------------------
extern "C" void kernel_launch(void* const* d_in, const int* in_sizes, int n_in,
                              void* d_out, int out_size) {
    const float* x       = (const float*)d_in[0];
    const int*   qweight = (const int*)d_in[1];
    const float* scales  = (const float*)d_in[2];
    const int*   qzeros  = (const int*)d_in[3];
    const float* bias    = (const float*)d_in[4];
    float* out = (float*)d_out;

    const int M = in_sizes[0] / K_DIM;  // 8192

    // Pass 1: fused x->fp16 + W dequant
    {
        int xblocks = (M * K_DIM / 8) / 256;        // 16384
        int wblocks = ((K_DIM / 8) * N_DIM) / 256;  // 8192
        prep_kernel<<<xblocks + wblocks, 256>>>(x, qweight, scales, qzeros, xblocks);
    }
    // Pass 2: GEMM
    {
        cudaFuncSetAttribute(gemm_f16_kernel,
                             cudaFuncAttributeMaxDynamicSharedMemorySize, SMEM_TOTAL);
        dim3 grid(N_DIM / BN, M / BM);
        gemm_f16_kernel<<<grid, 256, SMEM_TOTAL>>>(bias, out);
    }
}